// round 3
// baseline (speedup 1.0000x reference)
#include <cuda_runtime.h>
#include <stdint.h>

// Compile-time constants for this problem instance:
//   B = 1048576, D = 3, L = 16, C = 2, H = 16, S = 1.0
//   res(l) = 16 << l, side(l) = res+1
//   dense levels: l = 0,1,2 ; hashed levels: l >= 3, hm = 2^19
//   offsets: 0, 4920, 40864, 315496, then +524288 per level (all even)
//   table = concat(ext[524288,2], own[.,2]); both halves even-sized.
//
// R3: branchless corner-pair datapath. Per (y,z) pair:
//   - one unconditional LDG.128 at (a & ~1): always 16B-aligned, always
//     contains corner a; contains corner b too iff (a^b)==1 (all dense pairs
//     with even index, all hashed pairs with even x0 since PRIMES[0]==1).
//   - one predicated LDG.64 for b on unpaired lanes only.
// 8 load instructions/thread total, no divergent branches (vs ~12 + 4x
// BSSY/BSYNC in R2). Sector traffic unchanged (~6/thread).

#define HASH_SPLIT 524288u
#define P2 2654435761u
#define P3 805459861u

__device__ __forceinline__ const float2* tptr(unsigned g,
                                              const float2* __restrict__ ext,
                                              const float2* __restrict__ own)
{
    return (g < HASH_SPLIT) ? (ext + g) : (own + (g - HASH_SPLIT));
}

__global__ void __launch_bounds__(256)
grid_encode_kernel(const float* __restrict__ pts,
                   const float2* __restrict__ ext,
                   const float2* __restrict__ own,
                   float2* __restrict__ out)
{
    const unsigned gtid = blockIdx.x * 256u + threadIdx.x;
    const unsigned b = gtid >> 4;
    const unsigned l = gtid & 15u;

    const float px_in = __ldg(&pts[3u * b + 0u]);
    const float py_in = __ldg(&pts[3u * b + 1u]);
    const float pz_in = __ldg(&pts[3u * b + 2u]);

    const unsigned res  = 16u << l;
    const float scale   = (float)(res - 1u);
    const unsigned side = res + 1u;

    const float posx = (px_in + 1.0f) * 0.5f * scale + 0.5f;
    const float posy = (py_in + 1.0f) * 0.5f * scale + 0.5f;
    const float posz = (pz_in + 1.0f) * 0.5f * scale + 0.5f;

    const float flx = floorf(posx);
    const float fly = floorf(posy);
    const float flz = floorf(posz);
    const float fx = posx - flx;
    const float fy = posy - fly;
    const float fz = posz - flz;
    const unsigned x0 = (unsigned)flx;
    const unsigned y0 = (unsigned)fly;
    const unsigned z0 = (unsigned)flz;

    const bool hashed = (l >= 3u);
    const unsigned off = hashed ? (315496u + (l - 3u) * 524288u)
                                : (l == 0u ? 0u : (l == 1u ? 4920u : 40864u));

    // Hash per-axis terms (uint32 wraparound; PRIMES = {1, P2, P3})
    const unsigned hy0 = y0 * P2;
    const unsigned hz0 = z0 * P3;
    const unsigned hys[2] = { hy0, hy0 + P2 };
    const unsigned hzs[2] = { hz0, hz0 + P3 };

    // Dense per-axis terms (no modulo: side^3 <= hm for l<=2)
    const unsigned side2 = side * side;
    const unsigned dys[2] = { y0 * side,  y0 * side + side };
    const unsigned dzs[2] = { z0 * side2, z0 * side2 + side2 };

    // Global indices for the 4 (y,z) pairs: ia = x-corner 0, ib = x-corner 1.
    unsigned ia[4], ib[4];
#pragma unroll
    for (int p = 0; p < 4; ++p) {
        const int cy = p & 1, cz = (p >> 1) & 1;
        unsigned a, bx;
        if (hashed) {
            const unsigned base = hys[cy] ^ hzs[cz];
            a  = (x0 ^ base) & (HASH_SPLIT - 1u);
            bx = ((x0 + 1u) ^ base) & (HASH_SPLIT - 1u);
        } else {
            const unsigned base = dys[cy] + dzs[cz];
            a  = x0 + base;
            bx = a + 1u;
        }
        ia[p] = off + a;
        ib[p] = off + bx;
    }

    // Stage 1: unconditional aligned LDG.128 per pair (covers corner a; covers
    // corner b too when paired). All level/half boundaries are even, so
    // [a&~1, a&~1+1] never crosses one.
    float4 w4[4];
#pragma unroll
    for (int p = 0; p < 4; ++p) {
        const unsigned lo = ia[p] & ~1u;
        w4[p] = __ldg((const float4*)tptr(lo, ext, own));
    }

    // Stage 2: predicated LDG.64 for corner b on unpaired lanes.
    float2 vb2[4];
#pragma unroll
    for (int p = 0; p < 4; ++p) {
        vb2[p] = make_float2(0.0f, 0.0f);
        if ((ia[p] ^ ib[p]) != 1u)
            vb2[p] = __ldg(tptr(ib[p], ext, own));
    }

    // Select corner values (branchless).
    const float wx0 = 1.0f - fx, wx1 = fx;
    const float wy[2] = { 1.0f - fy, fy };
    const float wz[2] = { 1.0f - fz, fz };

    float accx = 0.0f, accy = 0.0f;
#pragma unroll
    for (int p = 0; p < 4; ++p) {
        const bool paired = ((ia[p] ^ ib[p]) == 1u);
        const bool ahi = (ia[p] & 1u);
        const float vax = ahi ? w4[p].z : w4[p].x;
        const float vay = ahi ? w4[p].w : w4[p].y;
        const float pbx = ahi ? w4[p].x : w4[p].z;
        const float pby = ahi ? w4[p].y : w4[p].w;
        const float vbx = paired ? pbx : vb2[p].x;
        const float vby = paired ? pby : vb2[p].y;

        const int cy = p & 1, cz = (p >> 1) & 1;
        const float wyz = wy[cy] * wz[cz];
        accx += wyz * (wx0 * vax + wx1 * vbx);
        accy += wyz * (wx0 * vay + wx1 * vby);
    }

    out[gtid] = make_float2(accx, accy);
}

extern "C" void kernel_launch(void* const* d_in, const int* in_sizes, int n_in,
                              void* d_out, int out_size)
{
    const float*  pts = (const float*)d_in[0];        // [B, 3]
    const float2* ext = (const float2*)d_in[1];       // [524288, 2]
    const float2* own = (const float2*)d_in[2];       // [N_TABLE - 524288, 2]
    float2* out = (float2*)d_out;                     // [B*16] float2

    grid_encode_kernel<<<65536, 256>>>(pts, ext, own, out);
}